// round 10
// baseline (speedup 1.0000x reference)
#include <cuda_runtime.h>
#include <cuda_bf16.h>
#include <cstdint>
#include <math.h>

#define N_TOK 2048
#define DIM   1024
#define NEXP  16
#define HID   2048
#define OUTD  1024
#define TOPK  2
#define NPAIR (N_TOK*TOPK)

// ---------------- scratch ----------------------------------------------------
__device__ int   g_cnt[NEXP];
__device__ int   g_off[NEXP+1];
__device__ int   g_cur[NEXP];
__device__ int   g_tok[NPAIR];
__device__ float g_prob[NPAIR];
__device__ int   g_tidx[N_TOK*TOPK];
__device__ float g_tp[N_TOK*TOPK];
__device__ float g_h[(size_t)NPAIR*HID];   // 32 MB hidden activations

// ---------------- small kernels ----------------------------------------------
__global__ void init_kernel() {
    if (threadIdx.x < NEXP) g_cnt[threadIdx.x] = 0;
}

__global__ void router_kernel(const float* __restrict__ z,
                              const float* __restrict__ rw,
                              const float* __restrict__ rb) {
    int n    = blockIdx.x;
    int tid  = threadIdx.x;
    int warp = tid >> 5, lane = tid & 31;
    __shared__ float logits[NEXP];
    const float* zr = z + (size_t)n * DIM;
    for (int e = warp; e < NEXP; e += 4) {
        const float* wr = rw + (size_t)e * DIM;
        float s = 0.f;
        for (int d = lane; d < DIM; d += 32) s += zr[d] * wr[d];
        #pragma unroll
        for (int o = 16; o; o >>= 1) s += __shfl_xor_sync(0xffffffffu, s, o);
        if (lane == 0) logits[e] = s + rb[e];
    }
    __syncthreads();
    if (tid == 0) {
        int i0 = 0; float v0 = logits[0];
        for (int e = 1; e < NEXP; e++) if (logits[e] > v0) { v0 = logits[e]; i0 = e; }
        int i1 = -1; float v1 = -1e30f;
        for (int e = 0; e < NEXP; e++) if (e != i0 && logits[e] > v1) { v1 = logits[e]; i1 = e; }
        float e2 = expf(v1 - v0);
        float inv = 1.0f / (1.0f + e2);
        g_tidx[n*2+0] = i0; g_tidx[n*2+1] = i1;
        g_tp[n*2+0] = inv;  g_tp[n*2+1] = e2 * inv;
        atomicAdd(&g_cnt[i0], 1);
        atomicAdd(&g_cnt[i1], 1);
    }
}

__global__ void scan_kernel() {
    if (threadIdx.x == 0) {
        int acc = 0;
        for (int e = 0; e < NEXP; e++) { g_off[e] = acc; g_cur[e] = acc; acc += g_cnt[e]; }
        g_off[NEXP] = acc;
    }
}

__global__ void scatter_kernel() {
    int n = blockIdx.x * blockDim.x + threadIdx.x;
    if (n >= N_TOK) return;
    #pragma unroll
    for (int k = 0; k < TOPK; k++) {
        int e = g_tidx[n*2+k];
        int pos = atomicAdd(&g_cur[e], 1);
        g_tok[pos]  = n;
        g_prob[pos] = g_tp[n*2+k];
    }
}

// ---------------- helpers -----------------------------------------------------
__device__ __forceinline__ uint32_t smem_u32(const void* p) {
    uint32_t a;
    asm("{ .reg .u64 t; cvta.to.shared.u64 t, %1; cvt.u32.u64 %0, t; }" : "=r"(a) : "l"(p));
    return a;
}

__device__ __forceinline__ void split4(float4 v, uint2& hi, uint2& lo) {
    __nv_bfloat162 h01 = __floats2bfloat162_rn(v.x, v.y);
    __nv_bfloat162 h23 = __floats2bfloat162_rn(v.z, v.w);
    float rx = v.x - __bfloat162float(h01.x);
    float ry = v.y - __bfloat162float(h01.y);
    float rz = v.z - __bfloat162float(h23.x);
    float rw = v.w - __bfloat162float(h23.y);
    __nv_bfloat162 l01 = __floats2bfloat162_rn(rx, ry);
    __nv_bfloat162 l23 = __floats2bfloat162_rn(rz, rw);
    hi.x = *reinterpret_cast<uint32_t*>(&h01);
    hi.y = *reinterpret_cast<uint32_t*>(&h23);
    lo.x = *reinterpret_cast<uint32_t*>(&l01);
    lo.y = *reinterpret_cast<uint32_t*>(&l23);
}

__device__ __forceinline__ void mma16816(float* d, const uint32_t* a, const uint32_t* b) {
    asm volatile(
        "mma.sync.aligned.m16n8k16.row.col.f32.bf16.bf16.f32 "
        "{%0,%1,%2,%3}, {%4,%5,%6,%7}, {%8,%9}, {%0,%1,%2,%3};"
        : "+f"(d[0]), "+f"(d[1]), "+f"(d[2]), "+f"(d[3])
        : "r"(a[0]), "r"(a[1]), "r"(a[2]), "r"(a[3]), "r"(b[0]), "r"(b[1]));
}

__device__ __forceinline__ void ldmx4(uint32_t& r0, uint32_t& r1, uint32_t& r2, uint32_t& r3,
                                      uint32_t addr) {
    asm volatile("ldmatrix.sync.aligned.m8n8.x4.shared.b16 {%0,%1,%2,%3}, [%4];"
                 : "=r"(r0), "=r"(r1), "=r"(r2), "=r"(r3) : "r"(addr));
}

// named barriers: full[b] = 1+b (producers arrive, consumers sync)
//                 empty[b] = 3+b (consumers arrive, producers sync)
#define BAR_SYNC(id)   asm volatile("bar.sync %0, 384;"   :: "r"(id) : "memory")
#define BAR_ARRIVE(id) asm volatile("bar.arrive %0, 384;" :: "r"(id) : "memory")

// ---------------- warp-specialized grouped GEMM -------------------------------
// CTA tile 128(M pairs) x 128(N), K chunk = 32, double-buffered smem.
// 384 threads: warps 0-7 compute (2x4 grid, 64x32 warp tile), warps 8-11 produce.
#define KC 32
#define SA 40                       // bf16 element stride per smem row (80 B)
#define BUFE (128 * SA)             // elems per matrix per buffer
#define SMEM_BYTES (16 * BUFE)      // 4 matrices x 2 buffers x BUFE x 2B = 80 KB

// MODE 0: A = z[g_tok[pos]], epilogue = bias+gelu -> g_h
// MODE 1: A = g_h[pos],      epilogue = prob*(acc+bias) atomicAdd -> out
template<int KDIM, int NDIM, int MODE>
__global__ __launch_bounds__(384, 1)
void moe_gemm(const float* __restrict__ Asrc, const float* __restrict__ Bw,
              const float* __restrict__ bias, float* __restrict__ outp)
{
    constexpr int NC = KDIM / KC;
    int e   = blockIdx.z;
    int cnt = g_cnt[e];
    int m0  = blockIdx.y * 128;
    if (m0 >= cnt) return;
    int off = g_off[e];
    int n0  = blockIdx.x * 128;
    int cntRem = cnt - m0;

    extern __shared__ __align__(16) uint16_t smbuf[];
    uint16_t* Ah = smbuf;               // [2][BUFE]
    uint16_t* Al = smbuf + 2*BUFE;
    uint16_t* Bh = smbuf + 4*BUFE;
    uint16_t* Bl = smbuf + 6*BUFE;

    int tid  = threadIdx.x;
    int wid  = tid >> 5, lane = tid & 31;

    if (wid < 8) {
        // ======================= CONSUMER (compute) =======================
        int wm   = wid >> 2, wn = wid & 3;          // 2 x 4 warp grid
        int quad = lane >> 2, tq = lane & 3;

        uint32_t AhA = smem_u32(Ah), AlA = smem_u32(Al);
        uint32_t BhA = smem_u32(Bh), BlA = smem_u32(Bl);

        int a_row  = wm*64 + (lane & 15);
        int a_koff = (lane >> 4) * 8;
        int b_row  = wn*32 + (lane & 7) + ((lane >> 4) & 1) * 8;
        int b_koff = ((lane >> 3) & 1) * 8;

        float acc[4][4][4];
        #pragma unroll
        for (int i = 0; i < 4; i++)
            #pragma unroll
            for (int j = 0; j < 4; j++)
                #pragma unroll
                for (int q = 0; q < 4; q++) acc[i][j][q] = 0.f;

        for (int ch = 0; ch < NC; ch++) {
            int b = ch & 1;
            uint32_t bb = (uint32_t)(b * BUFE * 2);   // byte offset within each region
            BAR_SYNC(1 + b);                          // wait buffer full
            #pragma unroll
            for (int ks = 0; ks < 2; ks++) {
                int kb = ks * 16;
                uint32_t bH[4][2], bL[4][2];
                #pragma unroll
                for (int p = 0; p < 2; p++) {
                    uint32_t boffB = bb + (uint32_t)(((b_row + p*16) * SA + kb + b_koff) * 2);
                    ldmx4(bH[2*p][0], bH[2*p][1], bH[2*p+1][0], bH[2*p+1][1], BhA + boffB);
                    ldmx4(bL[2*p][0], bL[2*p][1], bL[2*p+1][0], bL[2*p+1][1], BlA + boffB);
                }
                #pragma unroll
                for (int fi = 0; fi < 4; fi++) {
                    uint32_t aoff = bb + (uint32_t)(((a_row + fi*16) * SA + kb + a_koff) * 2);
                    uint32_t aH[4], aL[4];
                    ldmx4(aH[0], aH[1], aH[2], aH[3], AhA + aoff);
                    ldmx4(aL[0], aL[1], aL[2], aL[3], AlA + aoff);
                    #pragma unroll
                    for (int nj = 0; nj < 4; nj++) mma16816(acc[fi][nj], aH, bH[nj]);
                    #pragma unroll
                    for (int nj = 0; nj < 4; nj++) mma16816(acc[fi][nj], aH, bL[nj]);
                    #pragma unroll
                    for (int nj = 0; nj < 4; nj++) mma16816(acc[fi][nj], aL, bH[nj]);
                }
            }
            BAR_ARRIVE(3 + b);                        // mark buffer empty
        }

        // ---------------- epilogue ----------------
        #pragma unroll
        for (int fi = 0; fi < 4; fi++) {
            #pragma unroll
            for (int half = 0; half < 2; half++) {
                int rr = wm*64 + fi*16 + quad + half*8;
                if (rr >= cntRem) continue;
                int pos = off + m0 + rr;
                if (MODE == 0) {
                    float* dst = g_h + (size_t)pos * NDIM + n0;
                    const float* bp = bias + (size_t)e * NDIM + n0;
                    #pragma unroll
                    for (int nj = 0; nj < 4; nj++) {
                        int col = wn*32 + nj*8 + tq*2;
                        float x0 = acc[fi][nj][half*2+0] + bp[col];
                        float x1 = acc[fi][nj][half*2+1] + bp[col+1];
                        float2 o;
                        o.x = 0.5f * x0 * (1.0f + erff(x0 * 0.70710678118654752f));
                        o.y = 0.5f * x1 * (1.0f + erff(x1 * 0.70710678118654752f));
                        *(float2*)(dst + col) = o;
                    }
                } else {
                    int   tok = g_tok[pos];
                    float p   = g_prob[pos];
                    float* dst = outp + (size_t)tok * NDIM + n0;
                    const float* bp = bias + (size_t)e * NDIM + n0;
                    #pragma unroll
                    for (int nj = 0; nj < 4; nj++) {
                        int col = wn*32 + nj*8 + tq*2;
                        atomicAdd(dst + col,     p * (acc[fi][nj][half*2+0] + bp[col]));
                        atomicAdd(dst + col + 1, p * (acc[fi][nj][half*2+1] + bp[col+1]));
                    }
                }
            }
        }
    } else {
        // ======================= PRODUCER (staging) =======================
        int ptid = tid - 256;                         // 0..127, one row each
        int rclamp = ptid < cntRem ? ptid : (cntRem - 1);
        const float* arow;
        if (MODE == 0) {
            int tok = g_tok[off + m0 + rclamp];
            arow = Asrc + (size_t)tok * KDIM;
        } else {
            arow = g_h + (size_t)(off + m0 + rclamp) * KDIM;
        }
        const float* brow = Bw + ((size_t)e * NDIM + n0 + ptid) * KDIM;

        float4 pa[8], pb[8];
        #pragma unroll
        for (int q = 0; q < 8; q++) {
            pa[q] = *(const float4*)(arow + q*4);
            pb[q] = *(const float4*)(brow + q*4);
        }

        int rbase = ptid * SA;
        for (int ch = 0; ch < NC; ch++) {
            int b = ch & 1;
            int be = b * BUFE;
            if (ch >= 2) BAR_SYNC(3 + b);             // wait buffer empty
            #pragma unroll
            for (int g = 0; g < 4; g++) {
                uint2 h0, l0, h1, l1;
                split4(pa[2*g],   h0, l0);
                split4(pa[2*g+1], h1, l1);
                *(uint4*)&Ah[be + rbase + g*8] = make_uint4(h0.x, h0.y, h1.x, h1.y);
                *(uint4*)&Al[be + rbase + g*8] = make_uint4(l0.x, l0.y, l1.x, l1.y);
                split4(pb[2*g],   h0, l0);
                split4(pb[2*g+1], h1, l1);
                *(uint4*)&Bh[be + rbase + g*8] = make_uint4(h0.x, h0.y, h1.x, h1.y);
                *(uint4*)&Bl[be + rbase + g*8] = make_uint4(l0.x, l0.y, l1.x, l1.y);
            }
            __threadfence_block();                    // STS visible before arrive
            BAR_ARRIVE(1 + b);                        // mark buffer full
            if (ch + 1 < NC) {
                const float* ap = arow + (ch+1)*KC;
                const float* bp = brow + (ch+1)*KC;
                #pragma unroll
                for (int q = 0; q < 8; q++) {
                    pa[q] = *(const float4*)(ap + q*4);
                    pb[q] = *(const float4*)(bp + q*4);
                }
            }
        }
    }
}

// ---------------- launch ------------------------------------------------------
extern "C" void kernel_launch(void* const* d_in, const int* in_sizes, int n_in,
                              void* d_out, int out_size) {
    const float* z  = (const float*)d_in[0];
    const float* rw = (const float*)d_in[1];
    const float* rb = (const float*)d_in[2];
    const float* w1 = (const float*)d_in[3];
    const float* b1 = (const float*)d_in[4];
    const float* w2 = (const float*)d_in[5];
    const float* b2 = (const float*)d_in[6];
    float* out = (float*)d_out;

    cudaFuncSetAttribute(moe_gemm<DIM, HID, 0>,
                         cudaFuncAttributeMaxDynamicSharedMemorySize, SMEM_BYTES);
    cudaFuncSetAttribute(moe_gemm<HID, OUTD, 1>,
                         cudaFuncAttributeMaxDynamicSharedMemorySize, SMEM_BYTES);

    init_kernel<<<1, 32>>>();
    router_kernel<<<N_TOK, 128>>>(z, rw, rb);
    scan_kernel<<<1, 32>>>();
    scatter_kernel<<<(N_TOK + 255) / 256, 256>>>();
    cudaMemsetAsync(out, 0, (size_t)N_TOK * OUTD * sizeof(float), 0);

    dim3 g1(HID / 128, (NPAIR + 127) / 128, NEXP);
    moe_gemm<DIM, HID, 0><<<g1, 384, SMEM_BYTES>>>(z, w1, b1, nullptr);
    dim3 g2(OUTD / 128, (NPAIR + 127) / 128, NEXP);
    moe_gemm<HID, OUTD, 1><<<g2, 384, SMEM_BYTES>>>(nullptr, w2, b2, out);
}

// round 11
// speedup vs baseline: 1.5602x; 1.5602x over previous
#include <cuda_runtime.h>
#include <cuda_fp16.h>
#include <cstdint>
#include <math.h>

#define N_TOK 2048
#define DIM   1024
#define NEXP  16
#define HID   2048
#define OUTD  1024
#define TOPK  2
#define NPAIR (N_TOK*TOPK)

// ---------------- scratch ----------------------------------------------------
__device__ int   g_cnt[NEXP];
__device__ int   g_off[NEXP+1];
__device__ int   g_cur[NEXP];
__device__ int   g_tok[NPAIR];
__device__ float g_prob[NPAIR];
__device__ int   g_tidx[N_TOK*TOPK];
__device__ float g_tp[N_TOK*TOPK];
__device__ float g_h[(size_t)NPAIR*HID];   // 32 MB hidden activations

// ---------------- small kernels ----------------------------------------------
__global__ void init_kernel() {
    if (threadIdx.x < NEXP) g_cnt[threadIdx.x] = 0;
}

__global__ void router_kernel(const float* __restrict__ z,
                              const float* __restrict__ rw,
                              const float* __restrict__ rb) {
    int n    = blockIdx.x;
    int tid  = threadIdx.x;
    int warp = tid >> 5, lane = tid & 31;
    __shared__ float logits[NEXP];
    const float* zr = z + (size_t)n * DIM;
    for (int e = warp; e < NEXP; e += 4) {
        const float* wr = rw + (size_t)e * DIM;
        float s = 0.f;
        for (int d = lane; d < DIM; d += 32) s += zr[d] * wr[d];
        #pragma unroll
        for (int o = 16; o; o >>= 1) s += __shfl_xor_sync(0xffffffffu, s, o);
        if (lane == 0) logits[e] = s + rb[e];
    }
    __syncthreads();
    if (tid == 0) {
        int i0 = 0; float v0 = logits[0];
        for (int e = 1; e < NEXP; e++) if (logits[e] > v0) { v0 = logits[e]; i0 = e; }
        int i1 = -1; float v1 = -1e30f;
        for (int e = 0; e < NEXP; e++) if (e != i0 && logits[e] > v1) { v1 = logits[e]; i1 = e; }
        float e2 = expf(v1 - v0);
        float inv = 1.0f / (1.0f + e2);
        g_tidx[n*2+0] = i0; g_tidx[n*2+1] = i1;
        g_tp[n*2+0] = inv;  g_tp[n*2+1] = e2 * inv;
        atomicAdd(&g_cnt[i0], 1);
        atomicAdd(&g_cnt[i1], 1);
    }
}

__global__ void scan_kernel() {
    if (threadIdx.x == 0) {
        int acc = 0;
        for (int e = 0; e < NEXP; e++) { g_off[e] = acc; g_cur[e] = acc; acc += g_cnt[e]; }
        g_off[NEXP] = acc;
    }
}

__global__ void scatter_kernel() {
    int n = blockIdx.x * blockDim.x + threadIdx.x;
    if (n >= N_TOK) return;
    #pragma unroll
    for (int k = 0; k < TOPK; k++) {
        int e = g_tidx[n*2+k];
        int pos = atomicAdd(&g_cur[e], 1);
        g_tok[pos]  = n;
        g_prob[pos] = g_tp[n*2+k];
    }
}

// ---------------- helpers -----------------------------------------------------
__device__ __forceinline__ uint32_t smem_u32(const void* p) {
    uint32_t a;
    asm("{ .reg .u64 t; cvta.to.shared.u64 t, %1; cvt.u32.u64 %0, t; }" : "=r"(a) : "l"(p));
    return a;
}

// split fp32x4 -> fp16 hi + fp16 lo (packed pairs)
__device__ __forceinline__ void splitA4(float4 v, uint2& hi, uint2& lo) {
    __half2 h01 = __floats2half2_rn(v.x, v.y);
    __half2 h23 = __floats2half2_rn(v.z, v.w);
    float rx = v.x - __half2float(__low2half(h01));
    float ry = v.y - __half2float(__high2half(h01));
    float rz = v.z - __half2float(__low2half(h23));
    float rw = v.w - __half2float(__high2half(h23));
    __half2 l01 = __floats2half2_rn(rx, ry);
    __half2 l23 = __floats2half2_rn(rz, rw);
    hi.x = *reinterpret_cast<uint32_t*>(&h01);
    hi.y = *reinterpret_cast<uint32_t*>(&h23);
    lo.x = *reinterpret_cast<uint32_t*>(&l01);
    lo.y = *reinterpret_cast<uint32_t*>(&l23);
}

// fp32x4 -> fp16x4 (round once)
__device__ __forceinline__ uint2 half4(float4 v) {
    __half2 h01 = __floats2half2_rn(v.x, v.y);
    __half2 h23 = __floats2half2_rn(v.z, v.w);
    uint2 r;
    r.x = *reinterpret_cast<uint32_t*>(&h01);
    r.y = *reinterpret_cast<uint32_t*>(&h23);
    return r;
}

__device__ __forceinline__ void mma16816(float* d, const uint32_t* a, const uint32_t* b) {
    asm volatile(
        "mma.sync.aligned.m16n8k16.row.col.f32.f16.f16.f32 "
        "{%0,%1,%2,%3}, {%4,%5,%6,%7}, {%8,%9}, {%0,%1,%2,%3};"
        : "+f"(d[0]), "+f"(d[1]), "+f"(d[2]), "+f"(d[3])
        : "r"(a[0]), "r"(a[1]), "r"(a[2]), "r"(a[3]), "r"(b[0]), "r"(b[1]));
}

__device__ __forceinline__ void ldmx4(uint32_t& r0, uint32_t& r1, uint32_t& r2, uint32_t& r3,
                                      uint32_t addr) {
    asm volatile("ldmatrix.sync.aligned.m8n8.x4.shared.b16 {%0,%1,%2,%3}, [%4];"
                 : "=r"(r0), "=r"(r1), "=r"(r2), "=r"(r3) : "r"(addr));
}

// ---------------- grouped GEMM via mma.sync fp16 (A split-2, 2 passes) --------
// CTA tile 128(M pairs) x 128(N), K chunk = 32. 256 threads = 8 warps (2x4).
// Warp tile 64x32: 4 m-frags (16) x 4 n-frags (8), m16n8k16.
// D = Ah*Bh + Al*Bh = A*Bh ; error = A*(B - Bh) ~ 2^-12 incoherent.
#define KC 32
#define SA 40                 // fp16 element stride per smem row (80 B)

// MODE 0: A = z[g_tok[pos]], epilogue = bias+gelu -> g_h
// MODE 1: A = g_h[pos],      epilogue = prob*(acc+bias) atomicAdd -> out
template<int KDIM, int NDIM, int MODE>
__global__ __launch_bounds__(256, 1)
void moe_gemm(const float* __restrict__ Asrc, const float* __restrict__ Bw,
              const float* __restrict__ bias, float* __restrict__ outp)
{
    constexpr int NC = KDIM / KC;
    int e   = blockIdx.z;
    int cnt = g_cnt[e];
    int m0  = blockIdx.y * 128;
    if (m0 >= cnt) return;
    int off = g_off[e];
    int n0  = blockIdx.x * 128;
    int cntRem = cnt - m0;

    __shared__ __align__(16) uint16_t Ah[128 * SA];
    __shared__ __align__(16) uint16_t Al[128 * SA];
    __shared__ __align__(16) uint16_t Bh[128 * SA];

    int tid  = threadIdx.x;
    int wid  = tid >> 5, lane = tid & 31;
    int wm   = wid >> 2, wn = wid & 3;          // 2 x 4 warp grid
    int quad = lane >> 2, tq = lane & 3;

    uint32_t AhAddr = smem_u32(Ah), AlAddr = smem_u32(Al);
    uint32_t BhAddr = smem_u32(Bh);

    // ldmatrix per-lane row/col bases (element units)
    int a_row  = wm*64 + (lane & 15);
    int a_koff = (lane >> 4) * 8;
    int b_row  = wn*32 + (lane & 7) + ((lane >> 4) & 1) * 8;
    int b_koff = ((lane >> 3) & 1) * 8;

    // staging: 2 threads per row, 16 fp32 each
    int srow = tid >> 1;
    int scol = (tid & 1) * 16;
    int rclamp = srow < cntRem ? srow : (cntRem - 1);
    const float* arow;
    if (MODE == 0) {
        int tok = g_tok[off + m0 + rclamp];
        arow = Asrc + (size_t)tok * KDIM;
    } else {
        arow = g_h + (size_t)(off + m0 + rclamp) * KDIM;
    }
    const float* brow = Bw + ((size_t)e * NDIM + n0 + srow) * KDIM;

    float acc[4][4][4];
    #pragma unroll
    for (int i = 0; i < 4; i++)
        #pragma unroll
        for (int j = 0; j < 4; j++)
            #pragma unroll
            for (int q = 0; q < 4; q++) acc[i][j][q] = 0.f;

    float4 pa[4], pb[4];
    #pragma unroll
    for (int q = 0; q < 4; q++) {
        pa[q] = *(const float4*)(arow + scol + q*4);
        pb[q] = *(const float4*)(brow + scol + q*4);
    }

    for (int ch = 0; ch < NC; ch++) {
        // stage current chunk (A -> fp16 hi/lo, B -> fp16)
        #pragma unroll
        for (int q = 0; q < 4; q++) {
            uint2 hi, lo;
            int idx = srow * SA + scol + q*4;
            splitA4(pa[q], hi, lo);
            *(uint2*)&Ah[idx] = hi;  *(uint2*)&Al[idx] = lo;
            *(uint2*)&Bh[idx] = half4(pb[q]);
        }
        __syncthreads();
        // prefetch next chunk into registers
        if (ch + 1 < NC) {
            const float* ap = arow + (ch+1)*KC + scol;
            const float* bp = brow + (ch+1)*KC + scol;
            #pragma unroll
            for (int q = 0; q < 4; q++) {
                pa[q] = *(const float4*)(ap + q*4);
                pb[q] = *(const float4*)(bp + q*4);
            }
        }
        // compute: 2 k16-steps, fragments via ldmatrix.x4
        #pragma unroll
        for (int ks = 0; ks < 2; ks++) {
            int kb = ks * 16;
            uint32_t bH[4][2];
            #pragma unroll
            for (int p = 0; p < 2; p++) {
                uint32_t boffB = (uint32_t)(((b_row + p*16) * SA + kb + b_koff) * 2);
                ldmx4(bH[2*p][0], bH[2*p][1], bH[2*p+1][0], bH[2*p+1][1], BhAddr + boffB);
            }
            #pragma unroll
            for (int fi = 0; fi < 4; fi++) {
                uint32_t aoff = (uint32_t)(((a_row + fi*16) * SA + kb + a_koff) * 2);
                uint32_t aH[4], aL[4];
                ldmx4(aH[0], aH[1], aH[2], aH[3], AhAddr + aoff);
                ldmx4(aL[0], aL[1], aL[2], aL[3], AlAddr + aoff);
                #pragma unroll
                for (int nj = 0; nj < 4; nj++) mma16816(acc[fi][nj], aH, bH[nj]);
                #pragma unroll
                for (int nj = 0; nj < 4; nj++) mma16816(acc[fi][nj], aL, bH[nj]);
            }
        }
        __syncthreads();
    }

    // ---------------- epilogue ----------------
    #pragma unroll
    for (int fi = 0; fi < 4; fi++) {
        #pragma unroll
        for (int half = 0; half < 2; half++) {
            int rr = wm*64 + fi*16 + quad + half*8;
            if (rr >= cntRem) continue;
            int pos = off + m0 + rr;
            if (MODE == 0) {
                float* dst = g_h + (size_t)pos * NDIM + n0;
                const float* bp = bias + (size_t)e * NDIM + n0;
                #pragma unroll
                for (int nj = 0; nj < 4; nj++) {
                    int col = wn*32 + nj*8 + tq*2;
                    float x0 = acc[fi][nj][half*2+0] + bp[col];
                    float x1 = acc[fi][nj][half*2+1] + bp[col+1];
                    float2 o;
                    o.x = 0.5f * x0 * (1.0f + erff(x0 * 0.70710678118654752f));
                    o.y = 0.5f * x1 * (1.0f + erff(x1 * 0.70710678118654752f));
                    *(float2*)(dst + col) = o;
                }
            } else {
                int   tok = g_tok[pos];
                float p   = g_prob[pos];
                float* dst = outp + (size_t)tok * NDIM + n0;
                const float* bp = bias + (size_t)e * NDIM + n0;
                #pragma unroll
                for (int nj = 0; nj < 4; nj++) {
                    int col = wn*32 + nj*8 + tq*2;
                    atomicAdd(dst + col,     p * (acc[fi][nj][half*2+0] + bp[col]));
                    atomicAdd(dst + col + 1, p * (acc[fi][nj][half*2+1] + bp[col+1]));
                }
            }
        }
    }
}

// ---------------- launch ------------------------------------------------------
extern "C" void kernel_launch(void* const* d_in, const int* in_sizes, int n_in,
                              void* d_out, int out_size) {
    const float* z  = (const float*)d_in[0];
    const float* rw = (const float*)d_in[1];
    const float* rb = (const float*)d_in[2];
    const float* w1 = (const float*)d_in[3];
    const float* b1 = (const float*)d_in[4];
    const float* w2 = (const float*)d_in[5];
    const float* b2 = (const float*)d_in[6];
    float* out = (float*)d_out;

    init_kernel<<<1, 32>>>();
    router_kernel<<<N_TOK, 128>>>(z, rw, rb);
    scan_kernel<<<1, 32>>>();
    scatter_kernel<<<(N_TOK + 255) / 256, 256>>>();
    cudaMemsetAsync(out, 0, (size_t)N_TOK * OUTD * sizeof(float), 0);

    dim3 g1(HID / 128, (NPAIR + 127) / 128, NEXP);
    moe_gemm<DIM, HID, 0><<<g1, 256>>>(z, w1, b1, nullptr);
    dim3 g2(OUTD / 128, (NPAIR + 127) / 128, NEXP);
    moe_gemm<HID, OUTD, 1><<<g2, 256>>>(nullptr, w2, b2, out);
}

// round 12
// speedup vs baseline: 1.5737x; 1.0087x over previous
#include <cuda_runtime.h>
#include <cuda_fp16.h>
#include <cstdint>
#include <math.h>

#define N_TOK 2048
#define DIM   1024
#define NEXP  16
#define HID   2048
#define OUTD  1024
#define TOPK  2
#define NPAIR (N_TOK*TOPK)

// ---------------- scratch ----------------------------------------------------
__device__ int   g_cnt[NEXP];
__device__ int   g_off[NEXP+1];
__device__ int   g_cur[NEXP];
__device__ int   g_tok[NPAIR];
__device__ float g_prob[NPAIR];
__device__ int   g_tidx[N_TOK*TOPK];
__device__ float g_tp[N_TOK*TOPK];
__device__ float g_h[(size_t)NPAIR*HID];   // 32 MB hidden activations

// ---------------- small kernels ----------------------------------------------
__global__ void init_kernel() {
    if (threadIdx.x < NEXP) g_cnt[threadIdx.x] = 0;
}

__global__ void router_kernel(const float* __restrict__ z,
                              const float* __restrict__ rw,
                              const float* __restrict__ rb) {
    int n    = blockIdx.x;
    int tid  = threadIdx.x;
    int warp = tid >> 5, lane = tid & 31;
    __shared__ float logits[NEXP];
    const float* zr = z + (size_t)n * DIM;
    for (int e = warp; e < NEXP; e += 4) {
        const float* wr = rw + (size_t)e * DIM;
        float s = 0.f;
        for (int d = lane; d < DIM; d += 32) s += zr[d] * wr[d];
        #pragma unroll
        for (int o = 16; o; o >>= 1) s += __shfl_xor_sync(0xffffffffu, s, o);
        if (lane == 0) logits[e] = s + rb[e];
    }
    __syncthreads();
    if (tid == 0) {
        int i0 = 0; float v0 = logits[0];
        for (int e = 1; e < NEXP; e++) if (logits[e] > v0) { v0 = logits[e]; i0 = e; }
        int i1 = -1; float v1 = -1e30f;
        for (int e = 0; e < NEXP; e++) if (e != i0 && logits[e] > v1) { v1 = logits[e]; i1 = e; }
        float e2 = expf(v1 - v0);
        float inv = 1.0f / (1.0f + e2);
        g_tidx[n*2+0] = i0; g_tidx[n*2+1] = i1;
        g_tp[n*2+0] = inv;  g_tp[n*2+1] = e2 * inv;
        atomicAdd(&g_cnt[i0], 1);
        atomicAdd(&g_cnt[i1], 1);
    }
}

__global__ void scan_kernel() {
    if (threadIdx.x == 0) {
        int acc = 0;
        for (int e = 0; e < NEXP; e++) { g_off[e] = acc; g_cur[e] = acc; acc += g_cnt[e]; }
        g_off[NEXP] = acc;
    }
}

__global__ void scatter_kernel() {
    int n = blockIdx.x * blockDim.x + threadIdx.x;
    if (n >= N_TOK) return;
    #pragma unroll
    for (int k = 0; k < TOPK; k++) {
        int e = g_tidx[n*2+k];
        int pos = atomicAdd(&g_cur[e], 1);
        g_tok[pos]  = n;
        g_prob[pos] = g_tp[n*2+k];
    }
}

// ---------------- helpers -----------------------------------------------------
__device__ __forceinline__ uint32_t smem_u32(const void* p) {
    uint32_t a;
    asm("{ .reg .u64 t; cvta.to.shared.u64 t, %1; cvt.u32.u64 %0, t; }" : "=r"(a) : "l"(p));
    return a;
}

// fp32x4 -> fp16x4 (round once)
__device__ __forceinline__ uint2 half4(float4 v) {
    __half2 h01 = __floats2half2_rn(v.x, v.y);
    __half2 h23 = __floats2half2_rn(v.z, v.w);
    uint2 r;
    r.x = *reinterpret_cast<uint32_t*>(&h01);
    r.y = *reinterpret_cast<uint32_t*>(&h23);
    return r;
}

__device__ __forceinline__ void mma16816(float* d, const uint32_t* a, const uint32_t* b) {
    asm volatile(
        "mma.sync.aligned.m16n8k16.row.col.f32.f16.f16.f32 "
        "{%0,%1,%2,%3}, {%4,%5,%6,%7}, {%8,%9}, {%0,%1,%2,%3};"
        : "+f"(d[0]), "+f"(d[1]), "+f"(d[2]), "+f"(d[3])
        : "r"(a[0]), "r"(a[1]), "r"(a[2]), "r"(a[3]), "r"(b[0]), "r"(b[1]));
}

__device__ __forceinline__ void ldmx4(uint32_t& r0, uint32_t& r1, uint32_t& r2, uint32_t& r3,
                                      uint32_t addr) {
    asm volatile("ldmatrix.sync.aligned.m8n8.x4.shared.b16 {%0,%1,%2,%3}, [%4];"
                 : "=r"(r0), "=r"(r1), "=r"(r2), "=r"(r3) : "r"(addr));
}

// ---------------- grouped GEMM via mma.sync fp16 (single pass) ----------------
// CTA tile 128(M pairs) x 128(N), K chunk = 32. 256 threads = 8 warps (2x4).
// Warp tile 64x32: 4 m-frags (16) x 4 n-frags (8), m16n8k16.
// D = Ah*Bh ; error ~ sqrt(2) * single-rounding ~ 4e-4.
#define KC 32
#define SA 40                 // fp16 element stride per smem row (80 B)

// MODE 0: A = z[g_tok[pos]], epilogue = bias+gelu -> g_h
// MODE 1: A = g_h[pos],      epilogue = prob*(acc+bias) atomicAdd -> out
template<int KDIM, int NDIM, int MODE>
__global__ __launch_bounds__(256, 1)
void moe_gemm(const float* __restrict__ Asrc, const float* __restrict__ Bw,
              const float* __restrict__ bias, float* __restrict__ outp)
{
    constexpr int NC = KDIM / KC;
    int e   = blockIdx.z;
    int cnt = g_cnt[e];
    int m0  = blockIdx.y * 128;
    if (m0 >= cnt) return;
    int off = g_off[e];
    int n0  = blockIdx.x * 128;
    int cntRem = cnt - m0;

    __shared__ __align__(16) uint16_t Ah[128 * SA];
    __shared__ __align__(16) uint16_t Bh[128 * SA];

    int tid  = threadIdx.x;
    int wid  = tid >> 5, lane = tid & 31;
    int wm   = wid >> 2, wn = wid & 3;          // 2 x 4 warp grid
    int quad = lane >> 2, tq = lane & 3;

    uint32_t AhAddr = smem_u32(Ah);
    uint32_t BhAddr = smem_u32(Bh);

    // ldmatrix per-lane row/col bases (element units)
    int a_row  = wm*64 + (lane & 15);
    int a_koff = (lane >> 4) * 8;
    int b_row  = wn*32 + (lane & 7) + ((lane >> 4) & 1) * 8;
    int b_koff = ((lane >> 3) & 1) * 8;

    // staging: 2 threads per row, 16 fp32 each
    int srow = tid >> 1;
    int scol = (tid & 1) * 16;
    int rclamp = srow < cntRem ? srow : (cntRem - 1);
    const float* arow;
    if (MODE == 0) {
        int tok = g_tok[off + m0 + rclamp];
        arow = Asrc + (size_t)tok * KDIM;
    } else {
        arow = g_h + (size_t)(off + m0 + rclamp) * KDIM;
    }
    const float* brow = Bw + ((size_t)e * NDIM + n0 + srow) * KDIM;

    float acc[4][4][4];
    #pragma unroll
    for (int i = 0; i < 4; i++)
        #pragma unroll
        for (int j = 0; j < 4; j++)
            #pragma unroll
            for (int q = 0; q < 4; q++) acc[i][j][q] = 0.f;

    float4 pa[4], pb[4];
    #pragma unroll
    for (int q = 0; q < 4; q++) {
        pa[q] = *(const float4*)(arow + scol + q*4);
        pb[q] = *(const float4*)(brow + scol + q*4);
    }

    for (int ch = 0; ch < NC; ch++) {
        // stage current chunk (round fp32 -> fp16)
        #pragma unroll
        for (int q = 0; q < 4; q++) {
            int idx = srow * SA + scol + q*4;
            *(uint2*)&Ah[idx] = half4(pa[q]);
            *(uint2*)&Bh[idx] = half4(pb[q]);
        }
        __syncthreads();
        // prefetch next chunk into registers
        if (ch + 1 < NC) {
            const float* ap = arow + (ch+1)*KC + scol;
            const float* bp = brow + (ch+1)*KC + scol;
            #pragma unroll
            for (int q = 0; q < 4; q++) {
                pa[q] = *(const float4*)(ap + q*4);
                pb[q] = *(const float4*)(bp + q*4);
            }
        }
        // compute: 2 k16-steps, fragments via ldmatrix.x4
        #pragma unroll
        for (int ks = 0; ks < 2; ks++) {
            int kb = ks * 16;
            uint32_t bH[4][2];
            #pragma unroll
            for (int p = 0; p < 2; p++) {
                uint32_t boffB = (uint32_t)(((b_row + p*16) * SA + kb + b_koff) * 2);
                ldmx4(bH[2*p][0], bH[2*p][1], bH[2*p+1][0], bH[2*p+1][1], BhAddr + boffB);
            }
            #pragma unroll
            for (int fi = 0; fi < 4; fi++) {
                uint32_t aoff = (uint32_t)(((a_row + fi*16) * SA + kb + a_koff) * 2);
                uint32_t aH[4];
                ldmx4(aH[0], aH[1], aH[2], aH[3], AhAddr + aoff);
                #pragma unroll
                for (int nj = 0; nj < 4; nj++) mma16816(acc[fi][nj], aH, bH[nj]);
            }
        }
        __syncthreads();
    }

    // ---------------- epilogue ----------------
    #pragma unroll
    for (int fi = 0; fi < 4; fi++) {
        #pragma unroll
        for (int half = 0; half < 2; half++) {
            int rr = wm*64 + fi*16 + quad + half*8;
            if (rr >= cntRem) continue;
            int pos = off + m0 + rr;
            if (MODE == 0) {
                float* dst = g_h + (size_t)pos * NDIM + n0;
                const float* bp = bias + (size_t)e * NDIM + n0;
                #pragma unroll
                for (int nj = 0; nj < 4; nj++) {
                    int col = wn*32 + nj*8 + tq*2;
                    float x0 = acc[fi][nj][half*2+0] + bp[col];
                    float x1 = acc[fi][nj][half*2+1] + bp[col+1];
                    float2 o;
                    o.x = 0.5f * x0 * (1.0f + erff(x0 * 0.70710678118654752f));
                    o.y = 0.5f * x1 * (1.0f + erff(x1 * 0.70710678118654752f));
                    *(float2*)(dst + col) = o;
                }
            } else {
                int   tok = g_tok[pos];
                float p   = g_prob[pos];
                float* dst = outp + (size_t)tok * NDIM + n0;
                const float* bp = bias + (size_t)e * NDIM + n0;
                #pragma unroll
                for (int nj = 0; nj < 4; nj++) {
                    int col = wn*32 + nj*8 + tq*2;
                    atomicAdd(dst + col,     p * (acc[fi][nj][half*2+0] + bp[col]));
                    atomicAdd(dst + col + 1, p * (acc[fi][nj][half*2+1] + bp[col+1]));
                }
            }
        }
    }
}

// ---------------- launch ------------------------------------------------------
extern "C" void kernel_launch(void* const* d_in, const int* in_sizes, int n_in,
                              void* d_out, int out_size) {
    const float* z  = (const float*)d_in[0];
    const float* rw = (const float*)d_in[1];
    const float* rb = (const float*)d_in[2];
    const float* w1 = (const float*)d_in[3];
    const float* b1 = (const float*)d_in[4];
    const float* w2 = (const float*)d_in[5];
    const float* b2 = (const float*)d_in[6];
    float* out = (float*)d_out;

    init_kernel<<<1, 32>>>();
    router_kernel<<<N_TOK, 128>>>(z, rw, rb);
    scan_kernel<<<1, 32>>>();
    scatter_kernel<<<(N_TOK + 255) / 256, 256>>>();
    cudaMemsetAsync(out, 0, (size_t)N_TOK * OUTD * sizeof(float), 0);

    dim3 g1(HID / 128, (NPAIR + 127) / 128, NEXP);
    moe_gemm<DIM, HID, 0><<<g1, 256>>>(z, w1, b1, nullptr);
    dim3 g2(OUTD / 128, (NPAIR + 127) / 128, NEXP);
    moe_gemm<HID, OUTD, 1><<<g2, 256>>>(nullptr, w2, b2, out);
}

// round 13
// speedup vs baseline: 1.9224x; 1.2216x over previous
#include <cuda_runtime.h>
#include <cuda_fp16.h>
#include <cstdint>
#include <math.h>

#define N_TOK 2048
#define DIM   1024
#define NEXP  16
#define HID   2048
#define OUTD  1024
#define TOPK  2
#define NPAIR (N_TOK*TOPK)

// ---------------- scratch ----------------------------------------------------
__device__ int   g_cnt[NEXP];
__device__ int   g_off[NEXP+1];
__device__ int   g_cur[NEXP];
__device__ int   g_tok[NPAIR];
__device__ float g_prob[NPAIR];
__device__ int   g_tidx[N_TOK*TOPK];
__device__ float g_tp[N_TOK*TOPK];
__device__ float g_h[(size_t)NPAIR*HID];   // 32 MB hidden activations

// ---------------- small kernels ----------------------------------------------
__global__ void init_kernel() {
    if (threadIdx.x < NEXP) g_cnt[threadIdx.x] = 0;
}

__global__ void router_kernel(const float* __restrict__ z,
                              const float* __restrict__ rw,
                              const float* __restrict__ rb) {
    int n    = blockIdx.x;
    int tid  = threadIdx.x;
    int warp = tid >> 5, lane = tid & 31;
    __shared__ float logits[NEXP];
    const float* zr = z + (size_t)n * DIM;
    for (int e = warp; e < NEXP; e += 4) {
        const float* wr = rw + (size_t)e * DIM;
        float s = 0.f;
        for (int d = lane; d < DIM; d += 32) s += zr[d] * wr[d];
        #pragma unroll
        for (int o = 16; o; o >>= 1) s += __shfl_xor_sync(0xffffffffu, s, o);
        if (lane == 0) logits[e] = s + rb[e];
    }
    __syncthreads();
    if (tid == 0) {
        int i0 = 0; float v0 = logits[0];
        for (int e = 1; e < NEXP; e++) if (logits[e] > v0) { v0 = logits[e]; i0 = e; }
        int i1 = -1; float v1 = -1e30f;
        for (int e = 0; e < NEXP; e++) if (e != i0 && logits[e] > v1) { v1 = logits[e]; i1 = e; }
        float e2 = expf(v1 - v0);
        float inv = 1.0f / (1.0f + e2);
        g_tidx[n*2+0] = i0; g_tidx[n*2+1] = i1;
        g_tp[n*2+0] = inv;  g_tp[n*2+1] = e2 * inv;
        atomicAdd(&g_cnt[i0], 1);
        atomicAdd(&g_cnt[i1], 1);
    }
}

__global__ void scan_kernel() {
    if (threadIdx.x == 0) {
        int acc = 0;
        for (int e = 0; e < NEXP; e++) { g_off[e] = acc; g_cur[e] = acc; acc += g_cnt[e]; }
        g_off[NEXP] = acc;
    }
}

__global__ void scatter_kernel() {
    int n = blockIdx.x * blockDim.x + threadIdx.x;
    if (n >= N_TOK) return;
    #pragma unroll
    for (int k = 0; k < TOPK; k++) {
        int e = g_tidx[n*2+k];
        int pos = atomicAdd(&g_cur[e], 1);
        g_tok[pos]  = n;
        g_prob[pos] = g_tp[n*2+k];
    }
}

// ---------------- helpers -----------------------------------------------------
__device__ __forceinline__ uint32_t smem_u32(const void* p) {
    uint32_t a;
    asm("{ .reg .u64 t; cvta.to.shared.u64 t, %1; cvt.u32.u64 %0, t; }" : "=r"(a) : "l"(p));
    return a;
}

// fp32x4 -> fp16x4 (round once)
__device__ __forceinline__ uint2 half4(float4 v) {
    __half2 h01 = __floats2half2_rn(v.x, v.y);
    __half2 h23 = __floats2half2_rn(v.z, v.w);
    uint2 r;
    r.x = *reinterpret_cast<uint32_t*>(&h01);
    r.y = *reinterpret_cast<uint32_t*>(&h23);
    return r;
}

__device__ __forceinline__ void mma16816(float* d, const uint32_t* a, const uint32_t* b) {
    asm volatile(
        "mma.sync.aligned.m16n8k16.row.col.f32.f16.f16.f32 "
        "{%0,%1,%2,%3}, {%4,%5,%6,%7}, {%8,%9}, {%0,%1,%2,%3};"
        : "+f"(d[0]), "+f"(d[1]), "+f"(d[2]), "+f"(d[3])
        : "r"(a[0]), "r"(a[1]), "r"(a[2]), "r"(a[3]), "r"(b[0]), "r"(b[1]));
}

__device__ __forceinline__ void ldmx4(uint32_t& r0, uint32_t& r1, uint32_t& r2, uint32_t& r3,
                                      uint32_t addr) {
    asm volatile("ldmatrix.sync.aligned.m8n8.x4.shared.b16 {%0,%1,%2,%3}, [%4];"
                 : "=r"(r0), "=r"(r1), "=r"(r2), "=r"(r3) : "r"(addr));
}

// ---------------- grouped GEMM via mma.sync fp16 (1 pass, double-buffered) ----
// CTA tile 128(M pairs) x 128(N), K chunk = 32. 256 threads = 8 warps (2x4).
// Warp tile 64x32: 4 m-frags (16) x 4 n-frags (8), m16n8k16.
// One __syncthreads per chunk: buf[(ch+1)&1]'s last readers finished before
// sync(ch), so writing it during chunk ch+1's stage phase is hazard-free.
#define KC 32
#define SA 40                 // fp16 element stride per smem row (80 B)
#define BUFE (128 * SA)       // elements per matrix per buffer

// MODE 0: A = z[g_tok[pos]], epilogue = bias+gelu -> g_h
// MODE 1: A = g_h[pos],      epilogue = prob*(acc+bias) atomicAdd -> out
template<int KDIM, int NDIM, int MODE>
__global__ __launch_bounds__(256, 1)
void moe_gemm(const float* __restrict__ Asrc, const float* __restrict__ Bw,
              const float* __restrict__ bias, float* __restrict__ outp)
{
    constexpr int NC = KDIM / KC;
    int e   = blockIdx.z;
    int cnt = g_cnt[e];
    int m0  = blockIdx.y * 128;
    if (m0 >= cnt) return;
    int off = g_off[e];
    int n0  = blockIdx.x * 128;
    int cntRem = cnt - m0;

    __shared__ __align__(16) uint16_t Ah[2 * BUFE];
    __shared__ __align__(16) uint16_t Bh[2 * BUFE];

    int tid  = threadIdx.x;
    int wid  = tid >> 5, lane = tid & 31;
    int wm   = wid >> 2, wn = wid & 3;          // 2 x 4 warp grid
    int quad = lane >> 2, tq = lane & 3;

    uint32_t AhAddr = smem_u32(Ah);
    uint32_t BhAddr = smem_u32(Bh);

    // ldmatrix per-lane row/col bases (element units)
    int a_row  = wm*64 + (lane & 15);
    int a_koff = (lane >> 4) * 8;
    int b_row  = wn*32 + (lane & 7) + ((lane >> 4) & 1) * 8;
    int b_koff = ((lane >> 3) & 1) * 8;

    // staging: 2 threads per row, 16 fp32 each
    int srow = tid >> 1;
    int scol = (tid & 1) * 16;
    int rclamp = srow < cntRem ? srow : (cntRem - 1);
    const float* arow;
    if (MODE == 0) {
        int tok = g_tok[off + m0 + rclamp];
        arow = Asrc + (size_t)tok * KDIM;
    } else {
        arow = g_h + (size_t)(off + m0 + rclamp) * KDIM;
    }
    const float* brow = Bw + ((size_t)e * NDIM + n0 + srow) * KDIM;

    float acc[4][4][4];
    #pragma unroll
    for (int i = 0; i < 4; i++)
        #pragma unroll
        for (int j = 0; j < 4; j++)
            #pragma unroll
            for (int q = 0; q < 4; q++) acc[i][j][q] = 0.f;

    float4 pa[4], pb[4];
    #pragma unroll
    for (int q = 0; q < 4; q++) {
        pa[q] = *(const float4*)(arow + scol + q*4);
        pb[q] = *(const float4*)(brow + scol + q*4);
    }

    for (int ch = 0; ch < NC; ch++) {
        int be = (ch & 1) * BUFE;
        uint32_t bb = (uint32_t)(be * 2);       // byte offset of active buffer
        // stage current chunk (round fp32 -> fp16) into buf[ch&1]
        #pragma unroll
        for (int q = 0; q < 4; q++) {
            int idx = be + srow * SA + scol + q*4;
            *(uint2*)&Ah[idx] = half4(pa[q]);
            *(uint2*)&Bh[idx] = half4(pb[q]);
        }
        // prefetch next chunk into registers (a full compute-phase ahead)
        if (ch + 1 < NC) {
            const float* ap = arow + (ch+1)*KC + scol;
            const float* bp = brow + (ch+1)*KC + scol;
            #pragma unroll
            for (int q = 0; q < 4; q++) {
                pa[q] = *(const float4*)(ap + q*4);
                pb[q] = *(const float4*)(bp + q*4);
            }
        }
        __syncthreads();   // buf[ch&1] ready; buf[(ch+1)&1] already drained
        // compute: 2 k16-steps, fragments via ldmatrix.x4
        #pragma unroll
        for (int ks = 0; ks < 2; ks++) {
            int kb = ks * 16;
            uint32_t bH[4][2];
            #pragma unroll
            for (int p = 0; p < 2; p++) {
                uint32_t boffB = bb + (uint32_t)(((b_row + p*16) * SA + kb + b_koff) * 2);
                ldmx4(bH[2*p][0], bH[2*p][1], bH[2*p+1][0], bH[2*p+1][1], BhAddr + boffB);
            }
            #pragma unroll
            for (int fi = 0; fi < 4; fi++) {
                uint32_t aoff = bb + (uint32_t)(((a_row + fi*16) * SA + kb + a_koff) * 2);
                uint32_t aH[4];
                ldmx4(aH[0], aH[1], aH[2], aH[3], AhAddr + aoff);
                #pragma unroll
                for (int nj = 0; nj < 4; nj++) mma16816(acc[fi][nj], aH, bH[nj]);
            }
        }
        // no trailing barrier: next iteration writes the other buffer
    }

    // ---------------- epilogue ----------------
    #pragma unroll
    for (int fi = 0; fi < 4; fi++) {
        #pragma unroll
        for (int half = 0; half < 2; half++) {
            int rr = wm*64 + fi*16 + quad + half*8;
            if (rr >= cntRem) continue;
            int pos = off + m0 + rr;
            if (MODE == 0) {
                float* dst = g_h + (size_t)pos * NDIM + n0;
                const float* bp = bias + (size_t)e * NDIM + n0;
                #pragma unroll
                for (int nj = 0; nj < 4; nj++) {
                    int col = wn*32 + nj*8 + tq*2;
                    float x0 = acc[fi][nj][half*2+0] + bp[col];
                    float x1 = acc[fi][nj][half*2+1] + bp[col+1];
                    float2 o;
                    o.x = 0.5f * x0 * (1.0f + erff(x0 * 0.70710678118654752f));
                    o.y = 0.5f * x1 * (1.0f + erff(x1 * 0.70710678118654752f));
                    *(float2*)(dst + col) = o;
                }
            } else {
                int   tok = g_tok[pos];
                float p   = g_prob[pos];
                float* dst = outp + (size_t)tok * NDIM + n0;
                const float* bp = bias + (size_t)e * NDIM + n0;
                #pragma unroll
                for (int nj = 0; nj < 4; nj++) {
                    int col = wn*32 + nj*8 + tq*2;
                    atomicAdd(dst + col,     p * (acc[fi][nj][half*2+0] + bp[col]));
                    atomicAdd(dst + col + 1, p * (acc[fi][nj][half*2+1] + bp[col+1]));
                }
            }
        }
    }
}

// ---------------- launch ------------------------------------------------------
extern "C" void kernel_launch(void* const* d_in, const int* in_sizes, int n_in,
                              void* d_out, int out_size) {
    const float* z  = (const float*)d_in[0];
    const float* rw = (const float*)d_in[1];
    const float* rb = (const float*)d_in[2];
    const float* w1 = (const float*)d_in[3];
    const float* b1 = (const float*)d_in[4];
    const float* w2 = (const float*)d_in[5];
    const float* b2 = (const float*)d_in[6];
    float* out = (float*)d_out;

    init_kernel<<<1, 32>>>();
    router_kernel<<<N_TOK, 128>>>(z, rw, rb);
    scan_kernel<<<1, 32>>>();
    scatter_kernel<<<(N_TOK + 255) / 256, 256>>>();
    cudaMemsetAsync(out, 0, (size_t)N_TOK * OUTD * sizeof(float), 0);

    dim3 g1(HID / 128, (NPAIR + 127) / 128, NEXP);
    moe_gemm<DIM, HID, 0><<<g1, 256>>>(z, w1, b1, nullptr);
    dim3 g2(OUTD / 128, (NPAIR + 127) / 128, NEXP);
    moe_gemm<HID, OUTD, 1><<<g2, 256>>>(nullptr, w2, b2, out);
}

// round 14
// speedup vs baseline: 2.0270x; 1.0544x over previous
#include <cuda_runtime.h>
#include <cuda_fp16.h>
#include <cstdint>
#include <math.h>

#define N_TOK 2048
#define DIM   1024
#define NEXP  16
#define HID   2048
#define OUTD  1024
#define TOPK  2
#define NPAIR (N_TOK*TOPK)

// ---------------- scratch ----------------------------------------------------
__device__ int    g_cnt[NEXP];
__device__ int    g_off[NEXP+1];
__device__ int    g_cur[NEXP];
__device__ int    g_tok[NPAIR];
__device__ float  g_prob[NPAIR];
__device__ int    g_tidx[N_TOK*TOPK];
__device__ float  g_tp[N_TOK*TOPK];
__device__ __half g_h16[(size_t)NPAIR*HID];   // 16 MB hidden activations (fp16)

// ---------------- small kernels ----------------------------------------------
__global__ void init_kernel() {
    if (threadIdx.x < NEXP) g_cnt[threadIdx.x] = 0;
}

__global__ void router_kernel(const float* __restrict__ z,
                              const float* __restrict__ rw,
                              const float* __restrict__ rb) {
    int n    = blockIdx.x;
    int tid  = threadIdx.x;
    int warp = tid >> 5, lane = tid & 31;
    __shared__ float logits[NEXP];
    const float* zr = z + (size_t)n * DIM;
    for (int e = warp; e < NEXP; e += 4) {
        const float* wr = rw + (size_t)e * DIM;
        float s = 0.f;
        for (int d = lane; d < DIM; d += 32) s += zr[d] * wr[d];
        #pragma unroll
        for (int o = 16; o; o >>= 1) s += __shfl_xor_sync(0xffffffffu, s, o);
        if (lane == 0) logits[e] = s + rb[e];
    }
    __syncthreads();
    if (tid == 0) {
        int i0 = 0; float v0 = logits[0];
        for (int e = 1; e < NEXP; e++) if (logits[e] > v0) { v0 = logits[e]; i0 = e; }
        int i1 = -1; float v1 = -1e30f;
        for (int e = 0; e < NEXP; e++) if (e != i0 && logits[e] > v1) { v1 = logits[e]; i1 = e; }
        float e2 = expf(v1 - v0);
        float inv = 1.0f / (1.0f + e2);
        g_tidx[n*2+0] = i0; g_tidx[n*2+1] = i1;
        g_tp[n*2+0] = inv;  g_tp[n*2+1] = e2 * inv;
        atomicAdd(&g_cnt[i0], 1);
        atomicAdd(&g_cnt[i1], 1);
    }
}

__global__ void scan_kernel() {
    if (threadIdx.x == 0) {
        int acc = 0;
        for (int e = 0; e < NEXP; e++) { g_off[e] = acc; g_cur[e] = acc; acc += g_cnt[e]; }
        g_off[NEXP] = acc;
    }
}

__global__ void scatter_kernel() {
    int n = blockIdx.x * blockDim.x + threadIdx.x;
    if (n >= N_TOK) return;
    #pragma unroll
    for (int k = 0; k < TOPK; k++) {
        int e = g_tidx[n*2+k];
        int pos = atomicAdd(&g_cur[e], 1);
        g_tok[pos]  = n;
        g_prob[pos] = g_tp[n*2+k];
    }
}

// ---------------- helpers -----------------------------------------------------
__device__ __forceinline__ uint32_t smem_u32(const void* p) {
    uint32_t a;
    asm("{ .reg .u64 t; cvta.to.shared.u64 t, %1; cvt.u32.u64 %0, t; }" : "=r"(a) : "l"(p));
    return a;
}

// fp32x4 -> fp16x4 (round once)
__device__ __forceinline__ uint2 half4(float4 v) {
    __half2 h01 = __floats2half2_rn(v.x, v.y);
    __half2 h23 = __floats2half2_rn(v.z, v.w);
    uint2 r;
    r.x = *reinterpret_cast<uint32_t*>(&h01);
    r.y = *reinterpret_cast<uint32_t*>(&h23);
    return r;
}

__device__ __forceinline__ void mma16816(float* d, const uint32_t* a, const uint32_t* b) {
    asm volatile(
        "mma.sync.aligned.m16n8k16.row.col.f32.f16.f16.f32 "
        "{%0,%1,%2,%3}, {%4,%5,%6,%7}, {%8,%9}, {%0,%1,%2,%3};"
        : "+f"(d[0]), "+f"(d[1]), "+f"(d[2]), "+f"(d[3])
        : "r"(a[0]), "r"(a[1]), "r"(a[2]), "r"(a[3]), "r"(b[0]), "r"(b[1]));
}

__device__ __forceinline__ void ldmx4(uint32_t& r0, uint32_t& r1, uint32_t& r2, uint32_t& r3,
                                      uint32_t addr) {
    asm volatile("ldmatrix.sync.aligned.m8n8.x4.shared.b16 {%0,%1,%2,%3}, [%4];"
                 : "=r"(r0), "=r"(r1), "=r"(r2), "=r"(r3) : "r"(addr));
}

// ---------------- grouped GEMM via mma.sync fp16 (1 pass, dbuf, occ=2) --------
// CTA tile 128(M pairs) x 128(N), K chunk = 32. 256 threads = 8 warps (2x4).
// Warp tile 64x32: 4 m-frags (16) x 4 n-frags (8), m16n8k16.
#define KC 32
#define SA 40                 // fp16 element stride per smem row (80 B)
#define BUFE (128 * SA)       // elements per matrix per buffer

// MODE 0: A = z[g_tok[pos]] (fp32), epilogue = bias+gelu -> g_h16 (fp16)
// MODE 1: A = g_h16[pos] (fp16),    epilogue = prob*(acc+bias) atomicAdd -> out
template<int KDIM, int NDIM, int MODE>
__global__ __launch_bounds__(256, 2)
void moe_gemm(const float* __restrict__ Asrc, const float* __restrict__ Bw,
              const float* __restrict__ bias, float* __restrict__ outp)
{
    constexpr int NC = KDIM / KC;
    int e   = blockIdx.z;
    int cnt = g_cnt[e];
    int m0  = blockIdx.y * 128;
    if (m0 >= cnt) return;
    int off = g_off[e];
    int n0  = blockIdx.x * 128;
    int cntRem = cnt - m0;

    __shared__ __align__(16) uint16_t Ah[2 * BUFE];
    __shared__ __align__(16) uint16_t Bh[2 * BUFE];

    int tid  = threadIdx.x;
    int wid  = tid >> 5, lane = tid & 31;
    int wm   = wid >> 2, wn = wid & 3;          // 2 x 4 warp grid
    int quad = lane >> 2, tq = lane & 3;

    uint32_t AhAddr = smem_u32(Ah);
    uint32_t BhAddr = smem_u32(Bh);

    // ldmatrix per-lane row/col bases (element units)
    int a_row  = wm*64 + (lane & 15);
    int a_koff = (lane >> 4) * 8;
    int b_row  = wn*32 + (lane & 7) + ((lane >> 4) & 1) * 8;
    int b_koff = ((lane >> 3) & 1) * 8;

    // staging: 2 threads per row, 16 elements each
    int srow = tid >> 1;
    int scol = (tid & 1) * 16;
    int rclamp = srow < cntRem ? srow : (cntRem - 1);
    const float*  arowf = nullptr;
    const __half* arowh = nullptr;
    if (MODE == 0) {
        int tok = g_tok[off + m0 + rclamp];
        arowf = Asrc + (size_t)tok * KDIM;
    } else {
        arowh = g_h16 + (size_t)(off + m0 + rclamp) * KDIM;
    }
    const float* brow = Bw + ((size_t)e * NDIM + n0 + srow) * KDIM;

    float acc[4][4][4];
    #pragma unroll
    for (int i = 0; i < 4; i++)
        #pragma unroll
        for (int j = 0; j < 4; j++)
            #pragma unroll
            for (int q = 0; q < 4; q++) acc[i][j][q] = 0.f;

    float4 pa[4]; uint4 pa16[2]; float4 pb[4];
    if (MODE == 0) {
        #pragma unroll
        for (int q = 0; q < 4; q++) pa[q] = *(const float4*)(arowf + scol + q*4);
    } else {
        #pragma unroll
        for (int q = 0; q < 2; q++) pa16[q] = *(const uint4*)(arowh + scol + q*8);
    }
    #pragma unroll
    for (int q = 0; q < 4; q++) pb[q] = *(const float4*)(brow + scol + q*4);

    for (int ch = 0; ch < NC; ch++) {
        int be = (ch & 1) * BUFE;
        uint32_t bb = (uint32_t)(be * 2);       // byte offset of active buffer
        // stage current chunk into buf[ch&1]
        int idx = be + srow * SA + scol;
        if (MODE == 0) {
            #pragma unroll
            for (int q = 0; q < 4; q++) *(uint2*)&Ah[idx + q*4] = half4(pa[q]);
        } else {
            #pragma unroll
            for (int q = 0; q < 2; q++) *(uint4*)&Ah[idx + q*8] = pa16[q];
        }
        #pragma unroll
        for (int q = 0; q < 4; q++) *(uint2*)&Bh[idx + q*4] = half4(pb[q]);
        // prefetch next chunk into registers (a full compute-phase ahead)
        if (ch + 1 < NC) {
            if (MODE == 0) {
                const float* ap = arowf + (ch+1)*KC + scol;
                #pragma unroll
                for (int q = 0; q < 4; q++) pa[q] = *(const float4*)(ap + q*4);
            } else {
                const __half* ap = arowh + (ch+1)*KC + scol;
                #pragma unroll
                for (int q = 0; q < 2; q++) pa16[q] = *(const uint4*)(ap + q*8);
            }
            const float* bp = brow + (ch+1)*KC + scol;
            #pragma unroll
            for (int q = 0; q < 4; q++) pb[q] = *(const float4*)(bp + q*4);
        }
        __syncthreads();   // buf[ch&1] ready; buf[(ch+1)&1] already drained
        // compute: 2 k16-steps, fragments via ldmatrix.x4
        #pragma unroll
        for (int ks = 0; ks < 2; ks++) {
            int kb = ks * 16;
            uint32_t bH[4][2];
            #pragma unroll
            for (int p = 0; p < 2; p++) {
                uint32_t boffB = bb + (uint32_t)(((b_row + p*16) * SA + kb + b_koff) * 2);
                ldmx4(bH[2*p][0], bH[2*p][1], bH[2*p+1][0], bH[2*p+1][1], BhAddr + boffB);
            }
            #pragma unroll
            for (int fi = 0; fi < 4; fi++) {
                uint32_t aoff = bb + (uint32_t)(((a_row + fi*16) * SA + kb + a_koff) * 2);
                uint32_t aH[4];
                ldmx4(aH[0], aH[1], aH[2], aH[3], AhAddr + aoff);
                #pragma unroll
                for (int nj = 0; nj < 4; nj++) mma16816(acc[fi][nj], aH, bH[nj]);
            }
        }
        // no trailing barrier: next iteration writes the other buffer
    }

    // ---------------- epilogue ----------------
    #pragma unroll
    for (int fi = 0; fi < 4; fi++) {
        #pragma unroll
        for (int half = 0; half < 2; half++) {
            int rr = wm*64 + fi*16 + quad + half*8;
            if (rr >= cntRem) continue;
            int pos = off + m0 + rr;
            if (MODE == 0) {
                __half* dst = g_h16 + (size_t)pos * NDIM + n0;
                const float* bp = bias + (size_t)e * NDIM + n0;
                #pragma unroll
                for (int nj = 0; nj < 4; nj++) {
                    int col = wn*32 + nj*8 + tq*2;
                    float x0 = acc[fi][nj][half*2+0] + bp[col];
                    float x1 = acc[fi][nj][half*2+1] + bp[col+1];
                    float g0 = 0.5f * x0 * (1.0f + erff(x0 * 0.70710678118654752f));
                    float g1 = 0.5f * x1 * (1.0f + erff(x1 * 0.70710678118654752f));
                    __half2 o = __floats2half2_rn(g0, g1);
                    *(uint32_t*)(dst + col) = *reinterpret_cast<uint32_t*>(&o);
                }
            } else {
                int   tok = g_tok[pos];
                float p   = g_prob[pos];
                float* dst = outp + (size_t)tok * NDIM + n0;
                const float* bp = bias + (size_t)e * NDIM + n0;
                #pragma unroll
                for (int nj = 0; nj < 4; nj++) {
                    int col = wn*32 + nj*8 + tq*2;
                    atomicAdd(dst + col,     p * (acc[fi][nj][half*2+0] + bp[col]));
                    atomicAdd(dst + col + 1, p * (acc[fi][nj][half*2+1] + bp[col+1]));
                }
            }
        }
    }
}

// ---------------- launch ------------------------------------------------------
extern "C" void kernel_launch(void* const* d_in, const int* in_sizes, int n_in,
                              void* d_out, int out_size) {
    const float* z  = (const float*)d_in[0];
    const float* rw = (const float*)d_in[1];
    const float* rb = (const float*)d_in[2];
    const float* w1 = (const float*)d_in[3];
    const float* b1 = (const float*)d_in[4];
    const float* w2 = (const float*)d_in[5];
    const float* b2 = (const float*)d_in[6];
    float* out = (float*)d_out;

    init_kernel<<<1, 32>>>();
    router_kernel<<<N_TOK, 128>>>(z, rw, rb);
    scan_kernel<<<1, 32>>>();
    scatter_kernel<<<(N_TOK + 255) / 256, 256>>>();
    cudaMemsetAsync(out, 0, (size_t)N_TOK * OUTD * sizeof(float), 0);

    dim3 g1(HID / 128, (NPAIR + 127) / 128, NEXP);
    moe_gemm<DIM, HID, 0><<<g1, 256>>>(z, w1, b1, nullptr);
    dim3 g2(OUTD / 128, (NPAIR + 127) / 128, NEXP);
    moe_gemm<HID, OUTD, 1><<<g2, 256>>>(nullptr, w2, b2, out);
}

// round 15
// speedup vs baseline: 2.0395x; 1.0062x over previous
#include <cuda_runtime.h>
#include <cuda_fp16.h>
#include <cstdint>
#include <math.h>

#define N_TOK 2048
#define DIM   1024
#define NEXP  16
#define HID   2048
#define OUTD  1024
#define TOPK  2
#define NPAIR (N_TOK*TOPK)

// ---------------- scratch ----------------------------------------------------
__device__ int    g_cnt[NEXP];
__device__ int    g_off[NEXP+1];
__device__ int    g_cur[NEXP];
__device__ int    g_tok[NPAIR];
__device__ float  g_prob[NPAIR];
__device__ int    g_tidx[N_TOK*TOPK];
__device__ float  g_tp[N_TOK*TOPK];
__device__ __half g_h16[(size_t)NPAIR*HID];   // 16 MB hidden activations (fp16)

// ---------------- small kernels ----------------------------------------------
__global__ void init_kernel() {
    if (threadIdx.x < NEXP) g_cnt[threadIdx.x] = 0;
}

__global__ void router_kernel(const float* __restrict__ z,
                              const float* __restrict__ rw,
                              const float* __restrict__ rb) {
    int n    = blockIdx.x;
    int tid  = threadIdx.x;
    int warp = tid >> 5, lane = tid & 31;
    __shared__ float logits[NEXP];
    const float* zr = z + (size_t)n * DIM;
    for (int e = warp; e < NEXP; e += 4) {
        const float* wr = rw + (size_t)e * DIM;
        float s = 0.f;
        for (int d = lane; d < DIM; d += 32) s += zr[d] * wr[d];
        #pragma unroll
        for (int o = 16; o; o >>= 1) s += __shfl_xor_sync(0xffffffffu, s, o);
        if (lane == 0) logits[e] = s + rb[e];
    }
    __syncthreads();
    if (tid == 0) {
        int i0 = 0; float v0 = logits[0];
        for (int e = 1; e < NEXP; e++) if (logits[e] > v0) { v0 = logits[e]; i0 = e; }
        int i1 = -1; float v1 = -1e30f;
        for (int e = 0; e < NEXP; e++) if (e != i0 && logits[e] > v1) { v1 = logits[e]; i1 = e; }
        float e2 = expf(v1 - v0);
        float inv = 1.0f / (1.0f + e2);
        g_tidx[n*2+0] = i0; g_tidx[n*2+1] = i1;
        g_tp[n*2+0] = inv;  g_tp[n*2+1] = e2 * inv;
        atomicAdd(&g_cnt[i0], 1);
        atomicAdd(&g_cnt[i1], 1);
    }
}

__global__ void scan_kernel() {
    if (threadIdx.x == 0) {
        int acc = 0;
        for (int e = 0; e < NEXP; e++) { g_off[e] = acc; g_cur[e] = acc; acc += g_cnt[e]; }
        g_off[NEXP] = acc;
    }
}

__global__ void scatter_kernel() {
    int n = blockIdx.x * blockDim.x + threadIdx.x;
    if (n >= N_TOK) return;
    #pragma unroll
    for (int k = 0; k < TOPK; k++) {
        int e = g_tidx[n*2+k];
        int pos = atomicAdd(&g_cur[e], 1);
        g_tok[pos]  = n;
        g_prob[pos] = g_tp[n*2+k];
    }
}

// ---------------- helpers -----------------------------------------------------
__device__ __forceinline__ uint32_t smem_u32(const void* p) {
    uint32_t a;
    asm("{ .reg .u64 t; cvta.to.shared.u64 t, %1; cvt.u32.u64 %0, t; }" : "=r"(a) : "l"(p));
    return a;
}

// fp32x4 -> fp16x4 (round once)
__device__ __forceinline__ uint2 half4(float4 v) {
    __half2 h01 = __floats2half2_rn(v.x, v.y);
    __half2 h23 = __floats2half2_rn(v.z, v.w);
    uint2 r;
    r.x = *reinterpret_cast<uint32_t*>(&h01);
    r.y = *reinterpret_cast<uint32_t*>(&h23);
    return r;
}

__device__ __forceinline__ void mma16816(float* d, const uint32_t* a, const uint32_t* b) {
    asm volatile(
        "mma.sync.aligned.m16n8k16.row.col.f32.f16.f16.f32 "
        "{%0,%1,%2,%3}, {%4,%5,%6,%7}, {%8,%9}, {%0,%1,%2,%3};"
        : "+f"(d[0]), "+f"(d[1]), "+f"(d[2]), "+f"(d[3])
        : "r"(a[0]), "r"(a[1]), "r"(a[2]), "r"(a[3]), "r"(b[0]), "r"(b[1]));
}

__device__ __forceinline__ void ldmx4(uint32_t& r0, uint32_t& r1, uint32_t& r2, uint32_t& r3,
                                      uint32_t addr) {
    asm volatile("ldmatrix.sync.aligned.m8n8.x4.shared.b16 {%0,%1,%2,%3}, [%4];"
                 : "=r"(r0), "=r"(r1), "=r"(r2), "=r"(r3) : "r"(addr));
}

// ---------------- grouped GEMM: fp16 1-pass, dbuf, 512 threads, 128x256 tile --
// 16 warps in a 2(M) x 8(N) grid; warp tile 64x32 (4 m-frags x 4 n-frags).
#define KC 32
#define SA 40                   // fp16 element stride per smem row (80 B)
#define ABUF (128 * SA)         // A elems per buffer
#define BBUF (256 * SA)         // B elems per buffer
#define SMEM_BYTES ((2*ABUF + 2*BBUF) * 2)   // 61440 B

// MODE 0: A = z[g_tok[pos]] (fp32), epilogue = bias+gelu -> g_h16 (fp16)
// MODE 1: A = g_h16[pos] (fp16),    epilogue = prob*(acc+bias) atomicAdd -> out
template<int KDIM, int NDIM, int MODE>
__global__ __launch_bounds__(512, 1)
void moe_gemm(const float* __restrict__ Asrc, const float* __restrict__ Bw,
              const float* __restrict__ bias, float* __restrict__ outp)
{
    constexpr int NC = KDIM / KC;
    int e   = blockIdx.z;
    int cnt = g_cnt[e];
    int m0  = blockIdx.y * 128;
    if (m0 >= cnt) return;
    int off = g_off[e];
    int n0  = blockIdx.x * 256;
    int cntRem = cnt - m0;

    extern __shared__ __align__(16) uint16_t smbuf[];
    uint16_t* Ah = smbuf;               // [2][ABUF]
    uint16_t* Bh = smbuf + 2*ABUF;      // [2][BBUF]

    int tid  = threadIdx.x;
    int wid  = tid >> 5, lane = tid & 31;
    int wm   = wid >> 3, wn = wid & 7;          // 2 x 8 warp grid
    int quad = lane >> 2, tq = lane & 3;

    uint32_t AhAddr = smem_u32(Ah);
    uint32_t BhAddr = smem_u32(Bh);

    // ldmatrix per-lane row/col bases (element units)
    int a_row  = wm*64 + (lane & 15);
    int a_koff = (lane >> 4) * 8;
    int b_row  = wn*32 + (lane & 7) + ((lane >> 4) & 1) * 8;
    int b_koff = ((lane >> 3) & 1) * 8;

    // A staging: 4 threads per row, 8 elems each. B staging: 2/row, 16 each.
    int arA = tid >> 2, acA = (tid & 3) * 8;
    int arB = tid >> 1, acB = (tid & 1) * 16;
    int rclampA = arA < cntRem ? arA : (cntRem - 1);
    const float*  arowf = nullptr;
    const __half* arowh = nullptr;
    if (MODE == 0) {
        int tok = g_tok[off + m0 + rclampA];
        arowf = Asrc + (size_t)tok * KDIM;
    } else {
        arowh = g_h16 + (size_t)(off + m0 + rclampA) * KDIM;
    }
    const float* brow = Bw + ((size_t)e * NDIM + n0 + arB) * KDIM;

    float acc[4][4][4];
    #pragma unroll
    for (int i = 0; i < 4; i++)
        #pragma unroll
        for (int j = 0; j < 4; j++)
            #pragma unroll
            for (int q = 0; q < 4; q++) acc[i][j][q] = 0.f;

    float4 pa[2]; uint4 pa16; float4 pb[4];
    if (MODE == 0) {
        pa[0] = *(const float4*)(arowf + acA);
        pa[1] = *(const float4*)(arowf + acA + 4);
    } else {
        pa16 = *(const uint4*)(arowh + acA);
    }
    #pragma unroll
    for (int q = 0; q < 4; q++) pb[q] = *(const float4*)(brow + acB + q*4);

    for (int ch = 0; ch < NC; ch++) {
        int bsel = ch & 1;
        // stage current chunk into buf[bsel]
        {
            int idxA = bsel * ABUF + arA * SA + acA;
            if (MODE == 0) {
                *(uint2*)&Ah[idxA]     = half4(pa[0]);
                *(uint2*)&Ah[idxA + 4] = half4(pa[1]);
            } else {
                *(uint4*)&Ah[idxA] = pa16;
            }
            int idxB = bsel * BBUF + arB * SA + acB;
            #pragma unroll
            for (int q = 0; q < 4; q++) *(uint2*)&Bh[idxB + q*4] = half4(pb[q]);
        }
        // prefetch next chunk into registers (a full compute-phase ahead)
        if (ch + 1 < NC) {
            if (MODE == 0) {
                const float* ap = arowf + (ch+1)*KC + acA;
                pa[0] = *(const float4*)(ap);
                pa[1] = *(const float4*)(ap + 4);
            } else {
                pa16 = *(const uint4*)(arowh + (ch+1)*KC + acA);
            }
            const float* bp = brow + (ch+1)*KC + acB;
            #pragma unroll
            for (int q = 0; q < 4; q++) pb[q] = *(const float4*)(bp + q*4);
        }
        __syncthreads();   // buf[bsel] ready; other buffer already drained
        // compute: 2 k16-steps, fragments via ldmatrix.x4
        uint32_t bbA = (uint32_t)(bsel * ABUF * 2);
        uint32_t bbB = (uint32_t)(bsel * BBUF * 2);
        #pragma unroll
        for (int ks = 0; ks < 2; ks++) {
            int kb = ks * 16;
            uint32_t bH[4][2];
            #pragma unroll
            for (int p = 0; p < 2; p++) {
                uint32_t boffB = bbB + (uint32_t)(((b_row + p*16) * SA + kb + b_koff) * 2);
                ldmx4(bH[2*p][0], bH[2*p][1], bH[2*p+1][0], bH[2*p+1][1], BhAddr + boffB);
            }
            #pragma unroll
            for (int fi = 0; fi < 4; fi++) {
                uint32_t aoff = bbA + (uint32_t)(((a_row + fi*16) * SA + kb + a_koff) * 2);
                uint32_t aH[4];
                ldmx4(aH[0], aH[1], aH[2], aH[3], AhAddr + aoff);
                #pragma unroll
                for (int nj = 0; nj < 4; nj++) mma16816(acc[fi][nj], aH, bH[nj]);
            }
        }
        // no trailing barrier: next iteration writes the other buffer
    }

    // ---------------- epilogue ----------------
    #pragma unroll
    for (int fi = 0; fi < 4; fi++) {
        #pragma unroll
        for (int half = 0; half < 2; half++) {
            int rr = wm*64 + fi*16 + quad + half*8;
            if (rr >= cntRem) continue;
            int pos = off + m0 + rr;
            if (MODE == 0) {
                __half* dst = g_h16 + (size_t)pos * NDIM + n0;
                const float* bp = bias + (size_t)e * NDIM + n0;
                #pragma unroll
                for (int nj = 0; nj < 4; nj++) {
                    int col = wn*32 + nj*8 + tq*2;
                    float x0 = acc[fi][nj][half*2+0] + bp[col];
                    float x1 = acc[fi][nj][half*2+1] + bp[col+1];
                    float g0 = 0.5f * x0 * (1.0f + erff(x0 * 0.70710678118654752f));
                    float g1 = 0.5f * x1 * (1.0f + erff(x1 * 0.70710678118654752f));
                    __half2 o = __floats2half2_rn(g0, g1);
                    *(uint32_t*)(dst + col) = *reinterpret_cast<uint32_t*>(&o);
                }
            } else {
                int   tok = g_tok[pos];
                float p   = g_prob[pos];
                float* dst = outp + (size_t)tok * NDIM + n0;
                const float* bp = bias + (size_t)e * NDIM + n0;
                #pragma unroll
                for (int nj = 0; nj < 4; nj++) {
                    int col = wn*32 + nj*8 + tq*2;
                    atomicAdd(dst + col,     p * (acc[fi][nj][half*2+0] + bp[col]));
                    atomicAdd(dst + col + 1, p * (acc[fi][nj][half*2+1] + bp[col+1]));
                }
            }
        }
    }
}

// ---------------- launch ------------------------------------------------------
extern "C" void kernel_launch(void* const* d_in, const int* in_sizes, int n_in,
                              void* d_out, int out_size) {
    const float* z  = (const float*)d_in[0];
    const float* rw = (const float*)d_in[1];
    const float* rb = (const float*)d_in[2];
    const float* w1 = (const float*)d_in[3];
    const float* b1 = (const float*)d_in[4];
    const float* w2 = (const float*)d_in[5];
    const float* b2 = (const float*)d_in[6];
    float* out = (float*)d_out;

    cudaFuncSetAttribute(moe_gemm<DIM, HID, 0>,
                         cudaFuncAttributeMaxDynamicSharedMemorySize, SMEM_BYTES);
    cudaFuncSetAttribute(moe_gemm<HID, OUTD, 1>,
                         cudaFuncAttributeMaxDynamicSharedMemorySize, SMEM_BYTES);

    init_kernel<<<1, 32>>>();
    router_kernel<<<N_TOK, 128>>>(z, rw, rb);
    scan_kernel<<<1, 32>>>();
    scatter_kernel<<<(N_TOK + 255) / 256, 256>>>();
    cudaMemsetAsync(out, 0, (size_t)N_TOK * OUTD * sizeof(float), 0);

    dim3 g1(HID / 256, (NPAIR + 127) / 128, NEXP);
    moe_gemm<DIM, HID, 0><<<g1, 512, SMEM_BYTES>>>(z, w1, b1, nullptr);
    dim3 g2(OUTD / 256, (NPAIR + 127) / 128, NEXP);
    moe_gemm<HID, OUTD, 1><<<g2, 512, SMEM_BYTES>>>(nullptr, w2, b2, out);
}